// round 11
// baseline (speedup 1.0000x reference)
#include <cuda_runtime.h>
#include <cuda_fp16.h>
#include <cstdint>

#define BATCH   8192
#define HID     2560
#define NGATE   10240
#define NUM_KS  80
#define MT      64
#define NT      40

#define A_TILE   16384
#define B_TILE   32768
#define STAGE_SZ 49152
#define NSLOT    3
#define SM_BAR   147456
#define SMEM_TOT 147520

__device__ __align__(1024) unsigned char g_A[(size_t)MT * NUM_KS * A_TILE];
__device__ __align__(1024) unsigned char g_B[(size_t)NT * NUM_KS * B_TILE];
__device__ float g_bias[NGATE];

static __device__ __forceinline__ uint32_t smem_u32(const void* p) {
    uint32_t a;
    asm("{ .reg .u64 t; cvta.to.shared.u64 t, %1; cvt.u32.u64 %0, t; }" : "=r"(a) : "l"(p));
    return a;
}

#define MBAR_INIT(addr, cnt) \
    asm volatile("mbarrier.init.shared.b64 [%0], %1;" :: "r"(addr), "r"(cnt) : "memory")
#define MBAR_EXPECT_TX(addr, bytes) \
    asm volatile("mbarrier.arrive.expect_tx.shared.b64 _, [%0], %1;" :: "r"(addr), "r"(bytes) : "memory")
#define MBAR_ARRIVE(addr) \
    asm volatile("mbarrier.arrive.shared.b64 _, [%0];" :: "r"(addr) : "memory")

#define MBAR_WAIT(addr, ph) do {                                                    \
    uint32_t _m = (addr); uint32_t _p = (ph); uint32_t _d;                          \
    asm volatile("{\n\t.reg .pred p;\n\t"                                           \
        "mbarrier.try_wait.parity.acquire.cta.shared::cta.b64 p, [%1], %2;\n\t"     \
        "selp.b32 %0, 1, 0, p;\n\t}" : "=r"(_d) : "r"(_m), "r"(_p) : "memory");     \
    if (!_d) {                                                                      \
        asm volatile("{\n\t.reg .pred P1;\n\t"                                      \
            "WL_%=:\n\t"                                                            \
            "mbarrier.try_wait.parity.acquire.cta.shared::cta.b64 P1, [%0], %1, 0x989680;\n\t" \
            "@P1 bra.uni WD_%=;\n\tbra.uni WL_%=;\n\tWD_%=:\n\t}"                   \
            :: "r"(_m), "r"(_p) : "memory");                                        \
    }                                                                               \
} while (0)

static __device__ __forceinline__ void bulk_g2s(uint32_t sdst, const void* gsrc,
                                                uint32_t bytes, uint32_t mbar) {
    asm volatile(
        "cp.async.bulk.shared::cluster.global.mbarrier::complete_tx::bytes [%0], [%1], %2, [%3];"
        :: "r"(sdst), "l"(gsrc), "r"(bytes), "r"(mbar) : "memory");
}

#define LDSM4(r, addr)                                                              \
    asm volatile("ldmatrix.sync.aligned.m8n8.x4.shared.b16 {%0,%1,%2,%3}, [%4];"    \
        : "=r"((r)[0]), "=r"((r)[1]), "=r"((r)[2]), "=r"((r)[3]) : "r"(addr))

#define MMA16816(d, a, b0, b1)                                                      \
    asm volatile("mma.sync.aligned.m16n8k16.row.col.f32.f16.f16.f32 "               \
        "{%0,%1,%2,%3},{%4,%5,%6,%7},{%8,%9},{%0,%1,%2,%3};"                        \
        : "+f"((d)[0]), "+f"((d)[1]), "+f"((d)[2]), "+f"((d)[3])                    \
        : "r"((a)[0]), "r"((a)[1]), "r"((a)[2]), "r"((a)[3]), "r"(b0), "r"(b1))

static __device__ __forceinline__ float ftanh(float x) {
    float r;
    asm("tanh.approx.f32 %0, %1;" : "=f"(r) : "f"(x));
    return r;
}
static __device__ __forceinline__ float fsig(float x) {
    return fmaf(0.5f, ftanh(0.5f * x), 0.5f);
}

// ---- prep A: fp32 concat(input,h0) -> fp16 tiles 128 rows x 64 K, SW128 ----
__global__ __launch_bounds__(256) void prep_a(const float* __restrict__ inp,
                                              const float* __restrict__ h0) {
    int ks = blockIdx.x, mt = blockIdx.y;
    int kbase = ks * 64;
    const float* src = (kbase < HID) ? (inp + kbase) : (h0 + (kbase - HID));
    unsigned char* dst = g_A + (size_t)(mt * NUM_KS + ks) * A_TILE;
    int tid = threadIdx.x;
#pragma unroll 8
    for (int it = 0; it < 16; it++) {
        int idx = it * 256 + tid;
        int r = idx >> 5, kk2 = idx & 31;
        int m = mt * 128 + r;
        float2 v = *reinterpret_cast<const float2*>(src + (size_t)m * HID + 2 * kk2);
        __half2 h = __floats2half2_rn(v.x, v.y);
        uint32_t off = (uint32_t)(r * 128 + kk2 * 4);
        uint32_t sw = off ^ ((off >> 3) & 0x70);
        *reinterpret_cast<__half2*>(dst + sw) = h;
    }
}

// ---- prep B: coalesced reads; (g,i,f,o) of output h at
//      n = 16*(h>>2 local) + 8*(q>>1) + 2*(h&3) + (q&1); K-major SW128 tiles ----
__global__ __launch_bounds__(256) void prep_b(const float* __restrict__ wih,
                                              const float* __restrict__ whh) {
    __shared__ __half sm[64 * 259];       // stride 259: banks 3kp%32 -> conflict-free
    int ks = blockIdx.x, nt = blockIdx.y;
    int tid = threadIdx.x;
    int q = tid >> 6, jj = tid & 63;
    int col = ((nt >> 3) << 11) + (q << 9) + ((nt & 7) << 6) + jj;
    int n_local = 16 * (jj >> 2) + 8 * (q >> 1) + 2 * (jj & 3) + (q & 1);
    int kbase = ks * 64;
    const float* src = (kbase < HID) ? (wih + (size_t)kbase * NGATE)
                                     : (whh + (size_t)(kbase - HID) * NGATE);
#pragma unroll 4
    for (int it = 0; it < 64; it++) {
        float v = src[(size_t)it * NGATE + col];
        sm[it * 259 + n_local] = __float2half_rn(v);
    }
    __syncthreads();
    unsigned char* dst = g_B + (size_t)(nt * NUM_KS + ks) * B_TILE;
#pragma unroll 8
    for (int it = 0; it < 32; it++) {
        int idx = it * 256 + tid;
        int nl = idx >> 5, kp = idx & 31;
        __half a = sm[(2 * kp) * 259 + nl];
        __half b = sm[(2 * kp + 1) * 259 + nl];
        uint32_t off = (uint32_t)(nl * 128 + kp * 4);
        uint32_t sw = off ^ ((off >> 3) & 0x70);
        *reinterpret_cast<__half2*>(dst + sw) = __halves2half2(a, b);
    }
}

__global__ __launch_bounds__(256) void prep_bias(const float* __restrict__ bih,
                                                 const float* __restrict__ bhh) {
    int n = blockIdx.x * 256 + threadIdx.x;
    int a16 = n >> 4, half_ = (n >> 3) & 1, j2 = (n >> 1) & 3, b0 = n & 1;
    int h = 4 * a16 + j2, q = 2 * half_ + b0;
    int col = ((h >> 9) << 11) + (q << 9) + (h & 511);
    g_bias[n] = bih[col] + bhh[col];
}

// ---- fused HMMA GEMM (128M x 256 gate cols) + register LSTM epilogue ----
__global__ __launch_bounds__(288, 1) void lstm_gemm(const float* __restrict__ c0,
                                                    float* __restrict__ out) {
    extern __shared__ __align__(1024) unsigned char smem[];
    uint32_t sb = smem_u32(smem);
    int tid = threadIdx.x;
    int lane = tid & 31;
    int wid = tid >> 5;
    int nt = blockIdx.x, mt = blockIdx.y;
    int m0 = mt * 128, co0 = nt * 64;

    if (tid == 0) {
#pragma unroll
        for (int s = 0; s < NSLOT; s++) {
            MBAR_INIT(sb + SM_BAR + s * 8, 1);              // full[s], tx
            MBAR_INIT(sb + SM_BAR + NSLOT * 8 + s * 8, 8);  // empty[s], 8 warps
        }
    }
    __syncthreads();

    if (wid == 8) {
        // ---------------- producer warp ----------------
        if (lane == 0) {
            const unsigned char* Ab = g_A + (size_t)mt * NUM_KS * A_TILE;
            const unsigned char* Bb = g_B + (size_t)nt * NUM_KS * B_TILE;
            int slot = 0; uint32_t pph = 1;
            for (int s = 0; s < NUM_KS; s++) {
                MBAR_WAIT(sb + SM_BAR + NSLOT * 8 + slot * 8, pph);
                uint32_t full = sb + SM_BAR + slot * 8;
                MBAR_EXPECT_TX(full, STAGE_SZ);
                uint32_t dst = sb + slot * STAGE_SZ;
                bulk_g2s(dst,         Ab + (size_t)s * A_TILE, A_TILE, full);
                bulk_g2s(dst + 16384, Bb + (size_t)s * B_TILE, B_TILE, full);
                if (++slot == NSLOT) { slot = 0; pph ^= 1; }
            }
        }
        return;
    }

    // ---------------- compute warps ----------------
    float acc[4][8][4];
#pragma unroll
    for (int a = 0; a < 4; a++)
#pragma unroll
        for (int b = 0; b < 8; b++)
#pragma unroll
            for (int cI = 0; cI < 4; cI++) acc[a][b][cI] = 0.0f;

    int wm = wid & 1, wn = wid >> 1;
    uint32_t arow   = (uint32_t)(wm * 64 + (lane & 15));
    uint32_t apatch = (arow & 7) << 4;
    uint32_t abyte  = (uint32_t)((lane >> 4) * 16);
    uint32_t aoff0  = arow * 128;
    uint32_t gq     = (uint32_t)(lane >> 3);
    uint32_t brow0  = (uint32_t)(wn * 64 + ((gq >> 1) * 8) + (lane & 7));
    uint32_t bpatch = (brow0 & 7) << 4;
    uint32_t bbyte  = (gq & 1) * 16;
    uint32_t boff0  = 16384 + brow0 * 128;

    // kg-stagger: wm=1 warps process K chunks in order 2,3,0,1 (accumulation
    // order in K is commutative; A/B pairing preserved via shared perm)
    uint32_t perm = (uint32_t)(wm << 1);
    uint32_t axk[4], bxk[4];
#pragma unroll
    for (int kg = 0; kg < 4; kg++) {
        uint32_t kge = ((uint32_t)kg ^ perm) * 32u;
        axk[kg] = (abyte + kge) ^ apatch;
        bxk[kg] = (bbyte + kge) ^ bpatch;
    }

#define LOADA(buf, stA, kg) do {                                                    \
    _Pragma("unroll") for (int _mi = 0; _mi < 4; _mi++)                             \
        LDSM4((buf)[_mi], (stA) + _mi * 2048 + axk[kg]);                            \
} while (0)
#define LDSMB(buf, stB, kg, ni) LDSM4((buf), (stB) + (ni) * 2048 + bxk[kg])
#define MMA8(A, B, j) do {                                                          \
    _Pragma("unroll") for (int _mi = 0; _mi < 4; _mi++) {                           \
        MMA16816(acc[_mi][2 * (j)],     (A)[_mi], (B)[0], (B)[1]);                  \
        MMA16816(acc[_mi][2 * (j) + 1], (A)[_mi], (B)[2], (B)[3]);                  \
    }                                                                               \
} while (0)

    uint32_t aA[4][4], aB[4][4], bb[2][4];
    int slot = 0; uint32_t ph = 0;
#pragma unroll 1
    for (int s = 0; s < NUM_KS; s++) {
        MBAR_WAIT(sb + SM_BAR + slot * 8, ph);
        uint32_t stA = sb + slot * STAGE_SZ + aoff0;
        uint32_t stB = sb + slot * STAGE_SZ + boff0;
        LOADA(aA, stA, 0);
        LDSMB(bb[0], stB, 0, 0);
#pragma unroll
        for (int kg = 0; kg < 4; kg++) {
            if (kg < 3) {
                if (kg & 1) LOADA(aA, stA, kg + 1);
                else        LOADA(aB, stA, kg + 1);
            }
#pragma unroll
            for (int j = 0; j < 4; j++) {
                int cur = (kg * 4 + j) & 1;
                if (j < 3) {
                    LDSMB(bb[cur ^ 1], stB, kg, j + 1);
                } else if (kg < 3) {
                    LDSMB(bb[cur ^ 1], stB, kg + 1, 0);
                } else {
                    if (lane == 0) MBAR_ARRIVE(sb + SM_BAR + NSLOT * 8 + slot * 8);
                }
                if (kg & 1) MMA8(aB, bb[cur], j);
                else        MMA8(aA, bb[cur], j);
            }
        }
        if (++slot == NSLOT) { slot = 0; ph ^= 1; }
    }

    // ---------------- register LSTM epilogue (direct global c0/bias) ----------------
    const float* bias_t = g_bias + nt * 256;
    float* outh = out;
    float* outc = out + (size_t)BATCH * HID;
    int rb = wm * 64 + (lane >> 2);
#pragma unroll
    for (int mi = 0; mi < 4; mi++) {
#pragma unroll
        for (int a = 0; a < 4; a++) {
            float2 bgi = __ldg(reinterpret_cast<const float2*>(bias_t + wn * 64 + 16 * a + 2 * (lane & 3)));
            float2 bfo = __ldg(reinterpret_cast<const float2*>(bias_t + wn * 64 + 16 * a + 8 + 2 * (lane & 3)));
            int hl = 16 * wn + 4 * a + (lane & 3);
#pragma unroll
            for (int rr = 0; rr < 2; rr++) {
                int row = rb + mi * 16 + rr * 8;
                float g = acc[mi][2 * a][2 * rr]         + bgi.x;
                float i = acc[mi][2 * a][2 * rr + 1]     + bgi.y;
                float f = acc[mi][2 * a + 1][2 * rr]     + bfo.x;
                float o = acc[mi][2 * a + 1][2 * rr + 1] + bfo.y;
                size_t base = (size_t)(m0 + row) * HID + co0 + hl;
                float cc = __ldg(c0 + base);
                float c1 = ftanh(g) * fsig(i) + cc * fsig(f);
                float h1 = ftanh(c1) * fsig(o);
                outh[base] = h1;
                outc[base] = c1;
            }
        }
    }
}

extern "C" void kernel_launch(void* const* d_in, const int* in_sizes, int n_in,
                              void* d_out, int out_size) {
    const float* input = (const float*)d_in[0];
    const float* h0    = (const float*)d_in[1];
    const float* c0    = (const float*)d_in[2];
    const float* wih   = (const float*)d_in[3];
    const float* whh   = (const float*)d_in[4];
    const float* bih   = (const float*)d_in[5];
    const float* bhh   = (const float*)d_in[6];
    float* out = (float*)d_out;

    cudaFuncSetAttribute(lstm_gemm, cudaFuncAttributeMaxDynamicSharedMemorySize, SMEM_TOT);

    prep_a<<<dim3(NUM_KS, MT), 256>>>(input, h0);
    prep_b<<<dim3(NUM_KS, NT), 256>>>(wih, whh);
    prep_bias<<<NGATE / 256, 256>>>(bih, bhh);
    lstm_gemm<<<dim3(NT, MT), 288, SMEM_TOT>>>(c0, out);
}

// round 12
// speedup vs baseline: 1.0248x; 1.0248x over previous
#include <cuda_runtime.h>
#include <cuda_fp16.h>
#include <cstdint>

#define BATCH   8192
#define HID     2560
#define NGATE   10240
#define NUM_KS  80
#define MT      64
#define NT      40      // prep-B tiles (256 gate cols)
#define NT2     80      // gemm N-tiles (128 gate cols)

#define A_TILE   16384
#define B_TILE   32768
#define STAGE_SZ 32768   // [A 16K][B 16K]
#define NSLOT    3
#define SM_BAR   98304
#define SMEM_TOT 98368

__device__ __align__(1024) unsigned char g_A[(size_t)MT * NUM_KS * A_TILE];
__device__ __align__(1024) unsigned char g_B[(size_t)NT * NUM_KS * B_TILE];
__device__ float g_bias[NGATE];

static __device__ __forceinline__ uint32_t smem_u32(const void* p) {
    uint32_t a;
    asm("{ .reg .u64 t; cvta.to.shared.u64 t, %1; cvt.u32.u64 %0, t; }" : "=r"(a) : "l"(p));
    return a;
}

#define MBAR_INIT(addr, cnt) \
    asm volatile("mbarrier.init.shared.b64 [%0], %1;" :: "r"(addr), "r"(cnt) : "memory")
#define MBAR_EXPECT_TX(addr, bytes) \
    asm volatile("mbarrier.arrive.expect_tx.shared.b64 _, [%0], %1;" :: "r"(addr), "r"(bytes) : "memory")
#define MBAR_ARRIVE(addr) \
    asm volatile("mbarrier.arrive.shared.b64 _, [%0];" :: "r"(addr) : "memory")

#define MBAR_WAIT(addr, ph) do {                                                    \
    uint32_t _m = (addr); uint32_t _p = (ph); uint32_t _d;                          \
    asm volatile("{\n\t.reg .pred p;\n\t"                                           \
        "mbarrier.try_wait.parity.acquire.cta.shared::cta.b64 p, [%1], %2;\n\t"     \
        "selp.b32 %0, 1, 0, p;\n\t}" : "=r"(_d) : "r"(_m), "r"(_p) : "memory");     \
    if (!_d) {                                                                      \
        asm volatile("{\n\t.reg .pred P1;\n\t"                                      \
            "WL_%=:\n\t"                                                            \
            "mbarrier.try_wait.parity.acquire.cta.shared::cta.b64 P1, [%0], %1, 0x989680;\n\t" \
            "@P1 bra.uni WD_%=;\n\tbra.uni WL_%=;\n\tWD_%=:\n\t}"                   \
            :: "r"(_m), "r"(_p) : "memory");                                        \
    }                                                                               \
} while (0)

static __device__ __forceinline__ void bulk_g2s(uint32_t sdst, const void* gsrc,
                                                uint32_t bytes, uint32_t mbar) {
    asm volatile(
        "cp.async.bulk.shared::cluster.global.mbarrier::complete_tx::bytes [%0], [%1], %2, [%3];"
        :: "r"(sdst), "l"(gsrc), "r"(bytes), "r"(mbar) : "memory");
}

#define LDSM4(r, addr)                                                              \
    asm volatile("ldmatrix.sync.aligned.m8n8.x4.shared.b16 {%0,%1,%2,%3}, [%4];"    \
        : "=r"((r)[0]), "=r"((r)[1]), "=r"((r)[2]), "=r"((r)[3]) : "r"(addr))

#define MMA16816(d, a, b0, b1)                                                      \
    asm volatile("mma.sync.aligned.m16n8k16.row.col.f32.f16.f16.f32 "               \
        "{%0,%1,%2,%3},{%4,%5,%6,%7},{%8,%9},{%0,%1,%2,%3};"                        \
        : "+f"((d)[0]), "+f"((d)[1]), "+f"((d)[2]), "+f"((d)[3])                    \
        : "r"((a)[0]), "r"((a)[1]), "r"((a)[2]), "r"((a)[3]), "r"(b0), "r"(b1))

static __device__ __forceinline__ float ftanh(float x) {
    float r;
    asm("tanh.approx.f32 %0, %1;" : "=f"(r) : "f"(x));
    return r;
}
static __device__ __forceinline__ float fsig(float x) {
    return fmaf(0.5f, ftanh(0.5f * x), 0.5f);
}

// ---- prep A: fp32 concat(input,h0) -> fp16 tiles 128 rows x 64 K, SW128 ----
__global__ __launch_bounds__(256) void prep_a(const float* __restrict__ inp,
                                              const float* __restrict__ h0) {
    int ks = blockIdx.x, mt = blockIdx.y;
    int kbase = ks * 64;
    const float* src = (kbase < HID) ? (inp + kbase) : (h0 + (kbase - HID));
    unsigned char* dst = g_A + (size_t)(mt * NUM_KS + ks) * A_TILE;
    int tid = threadIdx.x;
#pragma unroll 8
    for (int it = 0; it < 16; it++) {
        int idx = it * 256 + tid;
        int r = idx >> 5, kk2 = idx & 31;
        int m = mt * 128 + r;
        float2 v = *reinterpret_cast<const float2*>(src + (size_t)m * HID + 2 * kk2);
        __half2 h = __floats2half2_rn(v.x, v.y);
        uint32_t off = (uint32_t)(r * 128 + kk2 * 4);
        uint32_t sw = off ^ ((off >> 3) & 0x70);
        *reinterpret_cast<__half2*>(dst + sw) = h;
    }
}

// ---- prep B: coalesced reads; (g,i,f,o) of output h at
//      n = 16*(h>>2 local) + 8*(q>>1) + 2*(h&3) + (q&1); K-major SW128 tiles ----
__global__ __launch_bounds__(256) void prep_b(const float* __restrict__ wih,
                                              const float* __restrict__ whh) {
    __shared__ __half sm[64 * 259];       // stride 259: banks 3kp%32 -> conflict-free
    int ks = blockIdx.x, nt = blockIdx.y;
    int tid = threadIdx.x;
    int q = tid >> 6, jj = tid & 63;
    int col = ((nt >> 3) << 11) + (q << 9) + ((nt & 7) << 6) + jj;
    int n_local = 16 * (jj >> 2) + 8 * (q >> 1) + 2 * (jj & 3) + (q & 1);
    int kbase = ks * 64;
    const float* src = (kbase < HID) ? (wih + (size_t)kbase * NGATE)
                                     : (whh + (size_t)(kbase - HID) * NGATE);
#pragma unroll 4
    for (int it = 0; it < 64; it++) {
        float v = src[(size_t)it * NGATE + col];
        sm[it * 259 + n_local] = __float2half_rn(v);
    }
    __syncthreads();
    unsigned char* dst = g_B + (size_t)(nt * NUM_KS + ks) * B_TILE;
#pragma unroll 8
    for (int it = 0; it < 32; it++) {
        int idx = it * 256 + tid;
        int nl = idx >> 5, kp = idx & 31;
        __half a = sm[(2 * kp) * 259 + nl];
        __half b = sm[(2 * kp + 1) * 259 + nl];
        uint32_t off = (uint32_t)(nl * 128 + kp * 4);
        uint32_t sw = off ^ ((off >> 3) & 0x70);
        *reinterpret_cast<__half2*>(dst + sw) = __halves2half2(a, b);
    }
}

__global__ __launch_bounds__(256) void prep_bias(const float* __restrict__ bih,
                                                 const float* __restrict__ bhh) {
    int n = blockIdx.x * 256 + threadIdx.x;
    int a16 = n >> 4, half_ = (n >> 3) & 1, j2 = (n >> 1) & 3, b0 = n & 1;
    int h = 4 * a16 + j2, q = 2 * half_ + b0;
    int col = ((h >> 9) << 11) + (q << 9) + (h & 511);
    g_bias[n] = bih[col] + bhh[col];
}

// ---- fused HMMA GEMM (128M x 128 gate cols), 2 CTAs/SM + register LSTM ----
__global__ __launch_bounds__(160, 2) void lstm_gemm(const float* __restrict__ c0,
                                                    float* __restrict__ out) {
    extern __shared__ __align__(1024) unsigned char smem[];
    uint32_t sb = smem_u32(smem);
    int tid = threadIdx.x;
    int lane = tid & 31;
    int wid = tid >> 5;
    int nt2 = blockIdx.x, mt = blockIdx.y;
    int m0 = mt * 128, co0 = nt2 * 32;

    if (tid == 0) {
#pragma unroll
        for (int s = 0; s < NSLOT; s++) {
            MBAR_INIT(sb + SM_BAR + s * 8, 1);              // full[s], tx
            MBAR_INIT(sb + SM_BAR + NSLOT * 8 + s * 8, 4);  // empty[s], 4 warps
        }
    }
    __syncthreads();

    if (wid == 4) {
        // ---------------- producer warp ----------------
        if (lane == 0) {
            const unsigned char* Ab = g_A + (size_t)mt * NUM_KS * A_TILE;
            const unsigned char* Bb = g_B + (size_t)(nt2 >> 1) * NUM_KS * B_TILE
                                          + (size_t)(nt2 & 1) * 16384;
            int slot = 0; uint32_t pph = 1;
            for (int s = 0; s < NUM_KS; s++) {
                MBAR_WAIT(sb + SM_BAR + NSLOT * 8 + slot * 8, pph);
                uint32_t full = sb + SM_BAR + slot * 8;
                MBAR_EXPECT_TX(full, STAGE_SZ);
                uint32_t dst = sb + slot * STAGE_SZ;
                bulk_g2s(dst,         Ab + (size_t)s * A_TILE, 16384, full);
                bulk_g2s(dst + 16384, Bb + (size_t)s * B_TILE, 16384, full);
                if (++slot == NSLOT) { slot = 0; pph ^= 1; }
            }
        }
        return;
    }

    // ---------------- compute warps (4): warp tile 64M x 64 gate cols ----------------
    float acc[4][8][4];
#pragma unroll
    for (int a = 0; a < 4; a++)
#pragma unroll
        for (int b = 0; b < 8; b++)
#pragma unroll
            for (int cI = 0; cI < 4; cI++) acc[a][b][cI] = 0.0f;

    int wm = wid & 1, wn = wid >> 1;           // wm: M half, wn: gate-col half
    uint32_t arow   = (uint32_t)(wm * 64 + (lane & 15));
    uint32_t apatch = (arow & 7) << 4;
    uint32_t abyte  = (uint32_t)((lane >> 4) * 16);
    uint32_t aoff0  = arow * 128;
    uint32_t gq     = (uint32_t)(lane >> 3);
    uint32_t brow0  = (uint32_t)(wn * 64 + ((gq >> 1) * 8) + (lane & 7));
    uint32_t bpatch = (brow0 & 7) << 4;
    uint32_t bbyte  = (gq & 1) * 16;
    uint32_t boff0  = 16384 + brow0 * 128;

    uint32_t axk[4], bxk[4];
#pragma unroll
    for (int kg = 0; kg < 4; kg++) {
        axk[kg] = (abyte + kg * 32u) ^ apatch;
        bxk[kg] = (bbyte + kg * 32u) ^ bpatch;
    }

#define LOADA(buf, stA, kg) do {                                                    \
    _Pragma("unroll") for (int _mi = 0; _mi < 4; _mi++)                             \
        LDSM4((buf)[_mi], (stA) + _mi * 2048 + axk[kg]);                            \
} while (0)
#define LDSMB(buf, stB, kg, ni) LDSM4((buf), (stB) + (ni) * 2048 + bxk[kg])
#define MMA8(A, B, j) do {                                                          \
    _Pragma("unroll") for (int _mi = 0; _mi < 4; _mi++) {                           \
        MMA16816(acc[_mi][2 * (j)],     (A)[_mi], (B)[0], (B)[1]);                  \
        MMA16816(acc[_mi][2 * (j) + 1], (A)[_mi], (B)[2], (B)[3]);                  \
    }                                                                               \
} while (0)

    uint32_t aA[4][4], aB[4][4], bb[2][4];
    int slot = 0; uint32_t ph = 0;
#pragma unroll 1
    for (int s = 0; s < NUM_KS; s++) {
        MBAR_WAIT(sb + SM_BAR + slot * 8, ph);
        uint32_t stA = sb + slot * STAGE_SZ + aoff0;
        uint32_t stB = sb + slot * STAGE_SZ + boff0;
        LOADA(aA, stA, 0);
        LDSMB(bb[0], stB, 0, 0);
#pragma unroll
        for (int kg = 0; kg < 4; kg++) {
            if (kg < 3) {
                if (kg & 1) LOADA(aA, stA, kg + 1);
                else        LOADA(aB, stA, kg + 1);
            }
#pragma unroll
            for (int j = 0; j < 4; j++) {
                int cur = (kg * 4 + j) & 1;
                if (j < 3) {
                    LDSMB(bb[cur ^ 1], stB, kg, j + 1);
                } else if (kg < 3) {
                    LDSMB(bb[cur ^ 1], stB, kg + 1, 0);
                } else {
                    if (lane == 0) MBAR_ARRIVE(sb + SM_BAR + NSLOT * 8 + slot * 8);
                }
                if (kg & 1) MMA8(aB, bb[cur], j);
                else        MMA8(aA, bb[cur], j);
            }
        }
        if (++slot == NSLOT) { slot = 0; ph ^= 1; }
    }

    // ---------------- register LSTM epilogue (direct global c0/bias) ----------------
    const float* bias_t = g_bias + nt2 * 128;
    float* outh = out;
    float* outc = out + (size_t)BATCH * HID;
    int rb = wm * 64 + (lane >> 2);
#pragma unroll
    for (int mi = 0; mi < 4; mi++) {
#pragma unroll
        for (int a = 0; a < 4; a++) {
            float2 bgi = __ldg(reinterpret_cast<const float2*>(bias_t + wn * 64 + 16 * a + 2 * (lane & 3)));
            float2 bfo = __ldg(reinterpret_cast<const float2*>(bias_t + wn * 64 + 16 * a + 8 + 2 * (lane & 3)));
            int hl = 16 * wn + 4 * a + (lane & 3);
#pragma unroll
            for (int rr = 0; rr < 2; rr++) {
                int row = rb + mi * 16 + rr * 8;
                float g = acc[mi][2 * a][2 * rr]         + bgi.x;
                float i = acc[mi][2 * a][2 * rr + 1]     + bgi.y;
                float f = acc[mi][2 * a + 1][2 * rr]     + bfo.x;
                float o = acc[mi][2 * a + 1][2 * rr + 1] + bfo.y;
                size_t base = (size_t)(m0 + row) * HID + co0 + hl;
                float cc = __ldg(c0 + base);
                float c1 = ftanh(g) * fsig(i) + cc * fsig(f);
                float h1 = ftanh(c1) * fsig(o);
                outh[base] = h1;
                outc[base] = c1;
            }
        }
    }
}

extern "C" void kernel_launch(void* const* d_in, const int* in_sizes, int n_in,
                              void* d_out, int out_size) {
    const float* input = (const float*)d_in[0];
    const float* h0    = (const float*)d_in[1];
    const float* c0    = (const float*)d_in[2];
    const float* wih   = (const float*)d_in[3];
    const float* whh   = (const float*)d_in[4];
    const float* bih   = (const float*)d_in[5];
    const float* bhh   = (const float*)d_in[6];
    float* out = (float*)d_out;

    cudaFuncSetAttribute(lstm_gemm, cudaFuncAttributeMaxDynamicSharedMemorySize, SMEM_TOT);

    prep_a<<<dim3(NUM_KS, MT), 256>>>(input, h0);
    prep_b<<<dim3(NUM_KS, NT), 256>>>(wih, whh);
    prep_bias<<<NGATE / 256, 256>>>(bih, bhh);
    lstm_gemm<<<dim3(NT2, MT), 160, SMEM_TOT>>>(c0, out);
}

// round 13
// speedup vs baseline: 1.0305x; 1.0056x over previous
#include <cuda_runtime.h>
#include <cuda_fp16.h>
#include <cstdint>

#define BATCH   8192
#define HID     2560
#define NGATE   10240
#define NUM_KS  80
#define MT      64
#define NT      40

#define A_TILE   16384
#define B_TILE   32768
#define STAGE_SZ 49152
#define NSLOT    3
#define SM_C0    147456
#define SM_BIAS  182272
#define SM_BAR   183296
#define SMEM_TOT 183360

// prep grid split
#define PREP_A_BLOCKS   (NUM_KS * MT)            // 5120
#define PREP_B_BLOCKS   (NUM_KS * NT)            // 3200
#define PREP_BIAS_BLOCKS (NGATE / 256)           // 40
#define PREP_TOTAL      (PREP_A_BLOCKS + PREP_B_BLOCKS + PREP_BIAS_BLOCKS)

__device__ __align__(1024) unsigned char g_A[(size_t)MT * NUM_KS * A_TILE];
__device__ __align__(1024) unsigned char g_B[(size_t)NT * NUM_KS * B_TILE];
__device__ float g_bias[NGATE];

static __device__ __forceinline__ uint32_t smem_u32(const void* p) {
    uint32_t a;
    asm("{ .reg .u64 t; cvta.to.shared.u64 t, %1; cvt.u32.u64 %0, t; }" : "=r"(a) : "l"(p));
    return a;
}

#define MBAR_INIT(addr, cnt) \
    asm volatile("mbarrier.init.shared.b64 [%0], %1;" :: "r"(addr), "r"(cnt) : "memory")
#define MBAR_EXPECT_TX(addr, bytes) \
    asm volatile("mbarrier.arrive.expect_tx.shared.b64 _, [%0], %1;" :: "r"(addr), "r"(bytes) : "memory")
#define MBAR_ARRIVE(addr) \
    asm volatile("mbarrier.arrive.shared.b64 _, [%0];" :: "r"(addr) : "memory")

#define MBAR_WAIT(addr, ph) do {                                                    \
    uint32_t _m = (addr); uint32_t _p = (ph); uint32_t _d;                          \
    asm volatile("{\n\t.reg .pred p;\n\t"                                           \
        "mbarrier.try_wait.parity.acquire.cta.shared::cta.b64 p, [%1], %2;\n\t"     \
        "selp.b32 %0, 1, 0, p;\n\t}" : "=r"(_d) : "r"(_m), "r"(_p) : "memory");     \
    if (!_d) {                                                                      \
        asm volatile("{\n\t.reg .pred P1;\n\t"                                      \
            "WL_%=:\n\t"                                                            \
            "mbarrier.try_wait.parity.acquire.cta.shared::cta.b64 P1, [%0], %1, 0x989680;\n\t" \
            "@P1 bra.uni WD_%=;\n\tbra.uni WL_%=;\n\tWD_%=:\n\t}"                   \
            :: "r"(_m), "r"(_p) : "memory");                                        \
    }                                                                               \
} while (0)

static __device__ __forceinline__ void bulk_g2s(uint32_t sdst, const void* gsrc,
                                                uint32_t bytes, uint32_t mbar) {
    asm volatile(
        "cp.async.bulk.shared::cluster.global.mbarrier::complete_tx::bytes [%0], [%1], %2, [%3];"
        :: "r"(sdst), "l"(gsrc), "r"(bytes), "r"(mbar) : "memory");
}

#define LDSM4(r, addr)                                                              \
    asm volatile("ldmatrix.sync.aligned.m8n8.x4.shared.b16 {%0,%1,%2,%3}, [%4];"    \
        : "=r"((r)[0]), "=r"((r)[1]), "=r"((r)[2]), "=r"((r)[3]) : "r"(addr))

#define MMA16816(d, a, b0, b1)                                                      \
    asm volatile("mma.sync.aligned.m16n8k16.row.col.f32.f16.f16.f32 "               \
        "{%0,%1,%2,%3},{%4,%5,%6,%7},{%8,%9},{%0,%1,%2,%3};"                        \
        : "+f"((d)[0]), "+f"((d)[1]), "+f"((d)[2]), "+f"((d)[3])                    \
        : "r"((a)[0]), "r"((a)[1]), "r"((a)[2]), "r"((a)[3]), "r"(b0), "r"(b1))

static __device__ __forceinline__ float ftanh(float x) {
    float r;
    asm("tanh.approx.f32 %0, %1;" : "=f"(r) : "f"(x));
    return r;
}
static __device__ __forceinline__ float fsig(float x) {
    return fmaf(0.5f, ftanh(0.5f * x), 0.5f);
}

// ==== merged prep: A-convert | B-transpose | bias, one concurrent grid ====
__global__ __launch_bounds__(256) void prep_all(const float* __restrict__ inp,
                                                const float* __restrict__ h0,
                                                const float* __restrict__ wih,
                                                const float* __restrict__ whh,
                                                const float* __restrict__ bih,
                                                const float* __restrict__ bhh) {
    __shared__ __half sm[64 * 259];   // only used by B path
    int bid = blockIdx.x;
    int tid = threadIdx.x;

    if (bid < PREP_A_BLOCKS) {
        // ---- A: fp32 concat(input,h0) -> fp16 tiles 128 rows x 64 K, SW128 ----
        int ks = bid % NUM_KS, mt = bid / NUM_KS;
        int kbase = ks * 64;
        const float* src = (kbase < HID) ? (inp + kbase) : (h0 + (kbase - HID));
        unsigned char* dst = g_A + (size_t)(mt * NUM_KS + ks) * A_TILE;
#pragma unroll 8
        for (int it = 0; it < 16; it++) {
            int idx = it * 256 + tid;
            int r = idx >> 5, kk2 = idx & 31;
            int m = mt * 128 + r;
            float2 v = *reinterpret_cast<const float2*>(src + (size_t)m * HID + 2 * kk2);
            __half2 h = __floats2half2_rn(v.x, v.y);
            uint32_t off = (uint32_t)(r * 128 + kk2 * 4);
            uint32_t sw = off ^ ((off >> 3) & 0x70);
            *reinterpret_cast<__half2*>(dst + sw) = h;
        }
    } else if (bid < PREP_A_BLOCKS + PREP_B_BLOCKS) {
        // ---- B: coalesced reads; (g,i,f,o) of output h at
        //      n = 16*(h>>2 local) + 8*(q>>1) + 2*(h&3) + (q&1); K-major SW128 ----
        int b = bid - PREP_A_BLOCKS;
        int ks = b % NUM_KS, nt = b / NUM_KS;
        int q = tid >> 6, jj = tid & 63;
        int col = ((nt >> 3) << 11) + (q << 9) + ((nt & 7) << 6) + jj;
        int n_local = 16 * (jj >> 2) + 8 * (q >> 1) + 2 * (jj & 3) + (q & 1);
        int kbase = ks * 64;
        const float* src = (kbase < HID) ? (wih + (size_t)kbase * NGATE)
                                         : (whh + (size_t)(kbase - HID) * NGATE);
#pragma unroll 4
        for (int it = 0; it < 64; it++) {
            float v = src[(size_t)it * NGATE + col];
            sm[it * 259 + n_local] = __float2half_rn(v);
        }
        __syncthreads();
        unsigned char* dst = g_B + (size_t)(nt * NUM_KS + ks) * B_TILE;
#pragma unroll 8
        for (int it = 0; it < 32; it++) {
            int idx = it * 256 + tid;
            int nl = idx >> 5, kp = idx & 31;
            __half a = sm[(2 * kp) * 259 + nl];
            __half bh = sm[(2 * kp + 1) * 259 + nl];
            uint32_t off = (uint32_t)(nl * 128 + kp * 4);
            uint32_t sw = off ^ ((off >> 3) & 0x70);
            *reinterpret_cast<__half2*>(dst + sw) = __halves2half2(a, bh);
        }
    } else {
        // ---- bias (permuted) ----
        int n = (bid - PREP_A_BLOCKS - PREP_B_BLOCKS) * 256 + tid;
        int a16 = n >> 4, half_ = (n >> 3) & 1, j2 = (n >> 1) & 3, b0 = n & 1;
        int h = 4 * a16 + j2, qq = 2 * half_ + b0;
        int col = ((h >> 9) << 11) + (qq << 9) + (h & 511);
        g_bias[n] = bih[col] + bhh[col];
    }
}

// ---- fused HMMA GEMM (128M x 256 gate cols) + register LSTM epilogue (R8) ----
__global__ __launch_bounds__(288, 1) void lstm_gemm(const float* __restrict__ c0,
                                                    float* __restrict__ out) {
    extern __shared__ __align__(1024) unsigned char smem[];
    uint32_t sb = smem_u32(smem);
    int tid = threadIdx.x;
    int lane = tid & 31;
    int wid = tid >> 5;
    int nt = blockIdx.x, mt = blockIdx.y;
    int m0 = mt * 128, co0 = nt * 64;

    if (tid == 0) {
#pragma unroll
        for (int s = 0; s < NSLOT; s++) {
            MBAR_INIT(sb + SM_BAR + s * 8, 1);              // full[s], tx
            MBAR_INIT(sb + SM_BAR + NSLOT * 8 + s * 8, 8);  // empty[s], 8 warps
        }
    }
    __syncthreads();

    if (wid == 8) {
        // ---------------- producer warp ----------------
        if (lane == 0) {
            const unsigned char* Ab = g_A + (size_t)mt * NUM_KS * A_TILE;
            const unsigned char* Bb = g_B + (size_t)nt * NUM_KS * B_TILE;
            int slot = 0; uint32_t pph = 1;
            for (int s = 0; s < NUM_KS; s++) {
                MBAR_WAIT(sb + SM_BAR + NSLOT * 8 + slot * 8, pph);
                uint32_t full = sb + SM_BAR + slot * 8;
                MBAR_EXPECT_TX(full, STAGE_SZ);
                uint32_t dst = sb + slot * STAGE_SZ;
                bulk_g2s(dst,         Ab + (size_t)s * A_TILE, A_TILE, full);
                bulk_g2s(dst + 16384, Bb + (size_t)s * B_TILE, B_TILE, full);
                if (++slot == NSLOT) { slot = 0; pph ^= 1; }
            }
        }
        return;
    }

    // ---------------- compute warps: prefetch c0/bias ----------------
    float acc[4][8][4];
#pragma unroll
    for (int a = 0; a < 4; a++)
#pragma unroll
        for (int b = 0; b < 8; b++)
#pragma unroll
            for (int cI = 0; cI < 4; cI++) acc[a][b][cI] = 0.0f;

    float* c0s = reinterpret_cast<float*>(smem + SM_C0);
#pragma unroll
    for (int it = 0; it < 8; it++) {
        int idx = it * 256 + tid;
        int r = idx >> 4, c4 = idx & 15;
        float4 v = *reinterpret_cast<const float4*>(c0 + (size_t)(m0 + r) * HID + co0 + c4 * 4);
        float* d = c0s + r * 68 + c4 * 4;
        d[0] = v.x; d[1] = v.y; d[2] = v.z; d[3] = v.w;
    }
    if (tid < 64) {
        float4 bv = *reinterpret_cast<const float4*>(g_bias + nt * 256 + tid * 4);
        float* d = reinterpret_cast<float*>(smem + SM_BIAS) + tid * 4;
        d[0] = bv.x; d[1] = bv.y; d[2] = bv.z; d[3] = bv.w;
    }
    asm volatile("bar.sync 1, 256;" ::: "memory");

    // ---------------- mainloop ----------------
    int wm = wid & 1, wn = wid >> 1;
    uint32_t arow   = (uint32_t)(wm * 64 + (lane & 15));
    uint32_t apatch = (arow & 7) << 4;
    uint32_t abyte  = (uint32_t)((lane >> 4) * 16);
    uint32_t aoff0  = arow * 128;
    uint32_t gq     = (uint32_t)(lane >> 3);
    uint32_t brow0  = (uint32_t)(wn * 64 + ((gq >> 1) * 8) + (lane & 7));
    uint32_t bpatch = (brow0 & 7) << 4;
    uint32_t bbyte  = (gq & 1) * 16;
    uint32_t boff0  = 16384 + brow0 * 128;

    uint32_t axk[4], bxk[4];
#pragma unroll
    for (int kg = 0; kg < 4; kg++) {
        axk[kg] = (abyte + kg * 32u) ^ apatch;
        bxk[kg] = (bbyte + kg * 32u) ^ bpatch;
    }

#define LOADA(buf, stA, kg) do {                                                    \
    _Pragma("unroll") for (int _mi = 0; _mi < 4; _mi++)                             \
        LDSM4((buf)[_mi], (stA) + _mi * 2048 + axk[kg]);                            \
} while (0)
#define LDSMB(buf, stB, kg, ni) LDSM4((buf), (stB) + (ni) * 2048 + bxk[kg])
#define MMA8(A, B, j) do {                                                          \
    _Pragma("unroll") for (int _mi = 0; _mi < 4; _mi++) {                           \
        MMA16816(acc[_mi][2 * (j)],     (A)[_mi], (B)[0], (B)[1]);                  \
        MMA16816(acc[_mi][2 * (j) + 1], (A)[_mi], (B)[2], (B)[3]);                  \
    }                                                                               \
} while (0)

    uint32_t aA[4][4], aB[4][4], bb[2][4];
    int slot = 0; uint32_t ph = 0;
#pragma unroll 1
    for (int s = 0; s < NUM_KS; s++) {
        MBAR_WAIT(sb + SM_BAR + slot * 8, ph);
        uint32_t stA = sb + slot * STAGE_SZ + aoff0;
        uint32_t stB = sb + slot * STAGE_SZ + boff0;
        LOADA(aA, stA, 0);
        LDSMB(bb[0], stB, 0, 0);
#pragma unroll
        for (int kg = 0; kg < 4; kg++) {
            if (kg < 3) {
                if (kg & 1) LOADA(aA, stA, kg + 1);
                else        LOADA(aB, stA, kg + 1);
            }
#pragma unroll
            for (int j = 0; j < 4; j++) {
                int cur = (kg * 4 + j) & 1;
                if (j < 3) {
                    LDSMB(bb[cur ^ 1], stB, kg, j + 1);
                } else if (kg < 3) {
                    LDSMB(bb[cur ^ 1], stB, kg + 1, 0);
                } else {
                    if (lane == 0) MBAR_ARRIVE(sb + SM_BAR + NSLOT * 8 + slot * 8);
                }
                if (kg & 1) MMA8(aB, bb[cur], j);
                else        MMA8(aA, bb[cur], j);
            }
        }
        if (++slot == NSLOT) { slot = 0; ph ^= 1; }
    }

    // ---------------- register LSTM epilogue ----------------
    const float* bs = reinterpret_cast<const float*>(smem + SM_BIAS);
    float* outh = out;
    float* outc = out + (size_t)BATCH * HID;
    int rb = wm * 64 + (lane >> 2);
#pragma unroll
    for (int mi = 0; mi < 4; mi++) {
#pragma unroll
        for (int a = 0; a < 4; a++) {
            float2 bgi = *reinterpret_cast<const float2*>(&bs[wn * 64 + 16 * a + 2 * (lane & 3)]);
            float2 bfo = *reinterpret_cast<const float2*>(&bs[wn * 64 + 16 * a + 8 + 2 * (lane & 3)]);
            int hl = 16 * wn + 4 * a + (lane & 3);
#pragma unroll
            for (int rr = 0; rr < 2; rr++) {
                int row = rb + mi * 16 + rr * 8;
                float g = acc[mi][2 * a][2 * rr]         + bgi.x;
                float i = acc[mi][2 * a][2 * rr + 1]     + bgi.y;
                float f = acc[mi][2 * a + 1][2 * rr]     + bfo.x;
                float o = acc[mi][2 * a + 1][2 * rr + 1] + bfo.y;
                float c1 = ftanh(g) * fsig(i) + c0s[row * 68 + hl] * fsig(f);
                float h1 = ftanh(c1) * fsig(o);
                size_t base = (size_t)(m0 + row) * HID + co0 + hl;
                outh[base] = h1;
                outc[base] = c1;
            }
        }
    }
}

extern "C" void kernel_launch(void* const* d_in, const int* in_sizes, int n_in,
                              void* d_out, int out_size) {
    const float* input = (const float*)d_in[0];
    const float* h0    = (const float*)d_in[1];
    const float* c0    = (const float*)d_in[2];
    const float* wih   = (const float*)d_in[3];
    const float* whh   = (const float*)d_in[4];
    const float* bih   = (const float*)d_in[5];
    const float* bhh   = (const float*)d_in[6];
    float* out = (float*)d_out;

    cudaFuncSetAttribute(lstm_gemm, cudaFuncAttributeMaxDynamicSharedMemorySize, SMEM_TOT);

    prep_all<<<PREP_TOTAL, 256>>>(input, h0, wih, whh, bih, bhh);
    lstm_gemm<<<dim3(NT, MT), 288, SMEM_TOT>>>(c0, out);
}